// round 10
// baseline (speedup 1.0000x reference)
#include <cuda_runtime.h>
#include <cuda_fp16.h>
#include <cstdint>
#include <math.h>

#define N_PTS 1000000
#define G     256
#define H1C   64
#define H2C   128
#define LAT   256
#define TILE  64
#define NT    15625         // 1e6 / 64 exactly
#define THREADS 128

// ---------------- scratch ------------------------------------------------
struct Scratch {
    unsigned pooled[G * LAT];
    float    csum[G * 3];
    float    cnt[G];
};
__device__ Scratch g_s;
#define SCRATCH_WORDS ((G * LAT) + G * 3 + G)

__device__ __forceinline__ unsigned encf(float f) {
    unsigned u = __float_as_uint(f);
    return (u & 0x80000000u) ? ~u : (u | 0x80000000u);
}
__device__ __forceinline__ float decf(unsigned u) {
    return (u & 0x80000000u) ? __uint_as_float(u ^ 0x80000000u)
                             : __uint_as_float(~u);
}
__device__ __forceinline__ float softplus_f(float x) {
    return fmaxf(x, 0.f) + log1pf(expf(-fabsf(x)));
}

// ---------------- mma.sync helpers --------------------------------------
__device__ __forceinline__ uint32_t smem_u32(const void* p) {
    uint32_t a;
    asm("{ .reg .u64 t; cvta.to.shared.u64 t, %1; cvt.u32.u64 %0, t; }"
        : "=r"(a) : "l"(p));
    return a;
}
__device__ __forceinline__ void ldsm4(uint32_t r[4], uint32_t a) {
    asm volatile("ldmatrix.sync.aligned.m8n8.x4.shared.b16 {%0,%1,%2,%3}, [%4];"
        : "=r"(r[0]), "=r"(r[1]), "=r"(r[2]), "=r"(r[3]) : "r"(a));
}
__device__ __forceinline__ void mma16816(float d[4], const uint32_t a[4],
                                         uint32_t b0, uint32_t b1) {
    asm volatile(
        "mma.sync.aligned.m16n8k16.row.col.f32.f16.f16.f32 "
        "{%0,%1,%2,%3}, {%4,%5,%6,%7}, {%8,%9}, {%0,%1,%2,%3};"
        : "+f"(d[0]), "+f"(d[1]), "+f"(d[2]), "+f"(d[3])
        : "r"(a[0]), "r"(a[1]), "r"(a[2]), "r"(a[3]), "r"(b0), "r"(b1));
}
__device__ __forceinline__ unsigned pack_f16(float lo, float hi) {
    unsigned r;
    asm("cvt.rn.f16x2.f32 %0, %1, %2;" : "=r"(r) : "f"(hi), "f"(lo));
    return r;  // low 16 bits = lo
}

// ---------------- SMEM layout (bytes; tiles 1024-aligned) ----------------
#define OFF_W3    0         // 2 kblk x 256 x 128B = 65536
#define OFF_W2    65536     // 128 x 128B = 16384
#define OFF_H2    81920     // 2 kblk x 64 x 128B = 16384
#define OFF_FEATS 98304     // 2 x (64*4 f) = 2048 (double buffered)
#define OFF_W1    100352    // 256 f = 1024
#define OFF_B1    101376    // 256
#define OFF_B2    101632    // 512
#define OFF_B3    102144    // 1024
#define OFF_SEGS  103168    // 2 x 64 ints (double buffered) = 512
#define SMEM_TOTAL 103680   // x2 CTAs = 207360 <= 228KB/SM

// layer1 -> mma A-fragment computation (validated mapping, round 9)
__device__ __forceinline__ void compute_A2(uint32_t A2[4][4],
                                           const float* __restrict__ feats,
                                           const float* __restrict__ W1s,
                                           const float* __restrict__ b1s,
                                           int ra, int cq) {
    float fa0 = feats[ra * 4 + 0], fa1 = feats[ra * 4 + 1];
    float fa2 = feats[ra * 4 + 2], fa3 = feats[ra * 4 + 3];
    float fb0 = feats[(ra + 8) * 4 + 0], fb1 = feats[(ra + 8) * 4 + 1];
    float fb2 = feats[(ra + 8) * 4 + 2], fb3 = feats[(ra + 8) * 4 + 3];
    #pragma unroll
    for (int kt = 0; kt < 4; kt++) {
        const int c0 = kt * 16 + cq;
        float2 sa0 = *(const float2*)&b1s[c0];
        float2 sa1 = *(const float2*)&b1s[c0 + 8];
        float2 ta0 = sa0, ta1 = sa1;
        #pragma unroll
        for (int j = 0; j < 4; j++) {
            float2 w0 = *(const float2*)&W1s[j * 64 + c0];
            float2 w1 = *(const float2*)&W1s[j * 64 + c0 + 8];
            float fj_a = (j == 0) ? fa0 : (j == 1) ? fa1 : (j == 2) ? fa2 : fa3;
            float fj_b = (j == 0) ? fb0 : (j == 1) ? fb1 : (j == 2) ? fb2 : fb3;
            sa0.x = fmaf(fj_a, w0.x, sa0.x); sa0.y = fmaf(fj_a, w0.y, sa0.y);
            sa1.x = fmaf(fj_a, w1.x, sa1.x); sa1.y = fmaf(fj_a, w1.y, sa1.y);
            ta0.x = fmaf(fj_b, w0.x, ta0.x); ta0.y = fmaf(fj_b, w0.y, ta0.y);
            ta1.x = fmaf(fj_b, w1.x, ta1.x); ta1.y = fmaf(fj_b, w1.y, ta1.y);
        }
        A2[kt][0] = pack_f16(fmaxf(sa0.x, 0.f), fmaxf(sa0.y, 0.f));
        A2[kt][1] = pack_f16(fmaxf(ta0.x, 0.f), fmaxf(ta0.y, 0.f));
        A2[kt][2] = pack_f16(fmaxf(sa1.x, 0.f), fmaxf(sa1.y, 0.f));
        A2[kt][3] = pack_f16(fmaxf(ta1.x, 0.f), fmaxf(ta1.y, 0.f));
    }
}

// ---------------- kernels ------------------------------------------------
__global__ void k_zero() {
    unsigned* p = (unsigned*)&g_s;
    int i = blockIdx.x * blockDim.x + threadIdx.x;
    int stride = gridDim.x * blockDim.x;
    for (int j = i; j < SCRATCH_WORDS; j += stride) p[j] = 0u;
}

__global__ void k_tail() {}   // launch-pattern pad so ncu (-s 5) captures k_mlp

__global__ __launch_bounds__(THREADS, 2)
void k_mlp(const float* __restrict__ pc,
           const float* __restrict__ W1, const float* __restrict__ b1,
           const float* __restrict__ W2, const float* __restrict__ b2,
           const float* __restrict__ W3, const float* __restrict__ b3,
           const int*   __restrict__ seg) {
    extern __shared__ __align__(1024) char smem[];
    const uint32_t sb = smem_u32(smem);
    const int tid  = threadIdx.x;
    const int w    = tid >> 5;      // 4 warps
    const int lane = tid & 31;
    const bool is64 = (seg[N_PTS - 1] == 0);

    float* featsA = (float*)(smem + OFF_FEATS);
    float* featsB = featsA + TILE * 4;
    float* W1s   = (float*)(smem + OFF_W1);
    float* b1s   = (float*)(smem + OFF_B1);
    float* b2s   = (float*)(smem + OFF_B2);
    float* b3s   = (float*)(smem + OFF_B3);
    int*   segsA = (int*)  (smem + OFF_SEGS);
    int*   segsB = segsA + TILE;

    // ---- one-time weight prep: transpose to [n][k] fp16, SW128 ----------
    for (int i = tid; i < H1C * H2C; i += THREADS) {      // W2 [k=64][n=128]
        int k = i >> 7, n = i & 127;
        unsigned off = (unsigned)(n * 128) + (((unsigned)(k * 2)) ^ ((n & 7) << 4));
        *(__half*)(smem + OFF_W2 + off) = __float2half_rn(W2[i]);
    }
    for (int i = tid; i < H2C * LAT; i += THREADS) {      // W3 [k=128][n=256]
        int k = i >> 8, n = i & 255;
        unsigned off = (unsigned)((k >> 6) * 32768) + (unsigned)(n * 128)
                     + ((((unsigned)(k & 63)) * 2) ^ ((n & 7) << 4));
        *(__half*)(smem + OFF_W3 + off) = __float2half_rn(W3[i]);
    }
    for (int i = tid; i < 4 * H1C; i += THREADS) W1s[i] = W1[i];
    for (int i = tid; i < H1C;     i += THREADS) b1s[i] = b1[i];
    for (int i = tid; i < H2C;     i += THREADS) b2s[i] = b2[i];
    for (int i = tid; i < LAT;     i += THREADS) b3s[i] = b3[i];

    // per-lane ldmatrix geometry (validated layout)
    const int lane7 = lane & 7;
    const int gA_r = ((lane >> 3) & 1) * 8 + lane7;
    const int gA_c = ((lane >> 4) & 1) * 8;
    const int gB_r = ((lane >> 4) & 1) * 8 + lane7;
    const int gB_c = ((lane >> 3) & 1) * 8;
    const unsigned xmA = (unsigned)lane7 << 4;
    const int rq = lane >> 2;
    const int cq = 2 * (lane & 3);
    const int ra = w * 16 + rq;

    // ---- prologue: load+commit tile0, centroid(tile0), prefetch tile1 ---
    float pf1 = 0.f, pf2 = 0.f, pf3 = 0.f, pf4 = 0.f;
    int   pfs = 0;
    if (tid < TILE) {
        long gp = (long)blockIdx.x * TILE + tid;
        float c1 = pc[gp * 5 + 1], c2 = pc[gp * 5 + 2];
        float c3 = pc[gp * 5 + 3], c4 = pc[gp * 5 + 4];
        featsA[tid * 4 + 0] = c4; featsA[tid * 4 + 1] = c1;
        featsA[tid * 4 + 2] = c2; featsA[tid * 4 + 3] = c3;
        int s = is64 ? seg[2 * gp] : seg[gp];
        segsA[tid] = s;
        float x = c1, y = c2, z = c3, cn = 1.f;
        int s0 = __shfl_sync(0xffffffffu, s, 0);
        if (__all_sync(0xffffffffu, s == s0)) {
            #pragma unroll
            for (int o = 16; o > 0; o >>= 1) {
                x  += __shfl_down_sync(0xffffffffu, x,  o);
                y  += __shfl_down_sync(0xffffffffu, y,  o);
                z  += __shfl_down_sync(0xffffffffu, z,  o);
                cn += __shfl_down_sync(0xffffffffu, cn, o);
            }
            if (lane == 0) {
                atomicAdd(&g_s.csum[s * 3 + 0], x);
                atomicAdd(&g_s.csum[s * 3 + 1], y);
                atomicAdd(&g_s.csum[s * 3 + 2], z);
                atomicAdd(&g_s.cnt[s], cn);
            }
        } else {
            atomicAdd(&g_s.csum[s * 3 + 0], x);
            atomicAdd(&g_s.csum[s * 3 + 1], y);
            atomicAdd(&g_s.csum[s * 3 + 2], z);
            atomicAdd(&g_s.cnt[s], 1.f);
        }
        long tn = (long)blockIdx.x + gridDim.x;
        if (tn < NT) {
            gp = tn * TILE + tid;
            pf1 = pc[gp * 5 + 1]; pf2 = pc[gp * 5 + 2];
            pf3 = pc[gp * 5 + 3]; pf4 = pc[gp * 5 + 4];
            pfs = is64 ? seg[2 * gp] : seg[gp];
        }
    }
    __syncthreads();

    uint32_t A2[4][4];
    compute_A2(A2, featsA, W1s, b1s, ra, cq);   // tile 0's fragments

    int it = 0;
    for (long t = blockIdx.x; t < NT; t += gridDim.x, it++) {
        int* segsCur = (it & 1) ? segsB : segsA;
        int* segsNxt = (it & 1) ? segsA : segsB;
        float* featsNxt = (it & 1) ? featsA : featsB;
        __syncthreads();                 // X: prev L3 done with h2; bufs free

        // ---- layer 2: C2(16x128 per warp) = A2 @ W2 ---------------------
        {
            float acc2[16][4];
            #pragma unroll
            for (int nb = 0; nb < 16; nb++)
                #pragma unroll
                for (int q = 0; q < 4; q++) acc2[nb][q] = 0.f;
            #pragma unroll
            for (int kt = 0; kt < 4; kt++) {
                const int k0 = kt * 16;
                #pragma unroll
                for (int nbp = 0; nbp < 8; nbp++) {
                    uint32_t Bt[4];
                    unsigned boff = (unsigned)((nbp * 16 + gB_r) * 128)
                                  + (((unsigned)((k0 + gB_c) * 2)) ^ xmA);
                    ldsm4(Bt, sb + OFF_W2 + boff);
                    mma16816(acc2[2 * nbp + 0], A2[kt], Bt[0], Bt[1]);
                    mma16816(acc2[2 * nbp + 1], A2[kt], Bt[2], Bt[3]);
                }
            }
            // epilogue: bias+relu -> h2 fp16 (n becomes k), swizzled STS
            #pragma unroll
            for (int nb = 0; nb < 16; nb++) {
                const int n = nb * 8 + cq;
                float2 bb = *(const float2*)&b2s[n];
                float v0 = fmaxf(acc2[nb][0] + bb.x, 0.f);
                float v1 = fmaxf(acc2[nb][1] + bb.y, 0.f);
                float v2 = fmaxf(acc2[nb][2] + bb.x, 0.f);
                float v3 = fmaxf(acc2[nb][3] + bb.y, 0.f);
                unsigned blk = (unsigned)((n >> 6) * 8192);
                unsigned cb  = ((unsigned)((n & 63) * 2)) ^ ((unsigned)rq << 4);
                *(unsigned*)(smem + OFF_H2 + blk + (unsigned)(ra * 128) + cb)
                    = pack_f16(v0, v1);
                *(unsigned*)(smem + OFF_H2 + blk + (unsigned)((ra + 8) * 128) + cb)
                    = pack_f16(v2, v3);
            }
        }

        // ---- commit NEXT tile (t+grid) + its centroid + prefetch t+2g ---
        const long tn = t + gridDim.x;
        if (tid < TILE) {
            featsNxt[tid * 4 + 0] = pf4; featsNxt[tid * 4 + 1] = pf1;
            featsNxt[tid * 4 + 2] = pf2; featsNxt[tid * 4 + 3] = pf3;
            segsNxt[tid] = pfs;
            if (tn < NT) {
                float x = pf1, y = pf2, z = pf3, cn = 1.f;
                int s = pfs;
                int s0 = __shfl_sync(0xffffffffu, s, 0);
                if (__all_sync(0xffffffffu, s == s0)) {
                    #pragma unroll
                    for (int o = 16; o > 0; o >>= 1) {
                        x  += __shfl_down_sync(0xffffffffu, x,  o);
                        y  += __shfl_down_sync(0xffffffffu, y,  o);
                        z  += __shfl_down_sync(0xffffffffu, z,  o);
                        cn += __shfl_down_sync(0xffffffffu, cn, o);
                    }
                    if (lane == 0) {
                        atomicAdd(&g_s.csum[s * 3 + 0], x);
                        atomicAdd(&g_s.csum[s * 3 + 1], y);
                        atomicAdd(&g_s.csum[s * 3 + 2], z);
                        atomicAdd(&g_s.cnt[s], cn);
                    }
                } else {
                    atomicAdd(&g_s.csum[s * 3 + 0], x);
                    atomicAdd(&g_s.csum[s * 3 + 1], y);
                    atomicAdd(&g_s.csum[s * 3 + 2], z);
                    atomicAdd(&g_s.cnt[s], 1.f);
                }
            }
            long tn2 = t + 2L * gridDim.x;
            if (tn2 < NT) {
                long gp = tn2 * TILE + tid;
                pf1 = pc[gp * 5 + 1]; pf2 = pc[gp * 5 + 2];
                pf3 = pc[gp * 5 + 3]; pf4 = pc[gp * 5 + 4];
                pfs = is64 ? seg[2 * gp] : seg[gp];
            }
        }
        __syncthreads();                 // Y: h2 + featsNxt ready

        // ---- next tile's A2 fragments (fma pipe; overlaps tensor) -------
        uint32_t A2n[4][4];
        compute_A2(A2n, featsNxt, W1s, b1s, ra, cq);

        // ---- layer 3: C3(64x256) = h2 @ W3; warp = (64 rows, 64 n) ------
        float acc3[4][8][4];
        #pragma unroll
        for (int i = 0; i < 4; i++)
            #pragma unroll
            for (int j = 0; j < 8; j++)
                #pragma unroll
                for (int q = 0; q < 4; q++) acc3[i][j][q] = 0.f;
        const int n0 = w * 64;
        #pragma unroll
        for (int kt = 0; kt < 8; kt++) {
            const int k0 = kt * 16;
            const unsigned kbA = (unsigned)((k0 >> 6) * 8192);
            const unsigned kbB = (unsigned)((k0 >> 6) * 32768);
            const unsigned kby = ((unsigned)(((k0 & 63) + gB_c) * 2)) ^ xmA;
            const unsigned kay = ((unsigned)(((k0 & 63) + gA_c) * 2)) ^ xmA;
            uint32_t Bh[4][4];
            #pragma unroll
            for (int nb = 0; nb < 4; nb++) {
                unsigned boff = kbB + (unsigned)((n0 + nb * 16 + gB_r) * 128) + kby;
                ldsm4(Bh[nb], sb + OFF_W3 + boff);
            }
            #pragma unroll
            for (int i = 0; i < 4; i++) {
                uint32_t Ah[4];
                ldsm4(Ah, sb + OFF_H2 + kbA
                      + (unsigned)((i * 16 + gA_r) * 128) + kay);
                #pragma unroll
                for (int nb = 0; nb < 4; nb++) {
                    mma16816(acc3[i][2 * nb + 0], Ah, Bh[nb][0], Bh[nb][1]);
                    mma16816(acc3[i][2 * nb + 1], Ah, Bh[nb][2], Bh[nb][3]);
                }
            }
        }

        // ---- segment-max pooling epilogue -------------------------------
        if (segsCur[0] == segsCur[TILE - 1]) {
            const int s0 = segsCur[0];
            #pragma unroll
            for (int j = 0; j < 8; j++) {
                float v0 = -3.402823466e38f, v1 = -3.402823466e38f;
                #pragma unroll
                for (int i = 0; i < 4; i++) {
                    v0 = fmaxf(v0, fmaxf(acc3[i][j][0], acc3[i][j][2]));
                    v1 = fmaxf(v1, fmaxf(acc3[i][j][1], acc3[i][j][3]));
                }
                #pragma unroll
                for (int o = 4; o < 32; o <<= 1) {
                    v0 = fmaxf(v0, __shfl_xor_sync(0xffffffffu, v0, o));
                    v1 = fmaxf(v1, __shfl_xor_sync(0xffffffffu, v1, o));
                }
                if (lane < 4) {
                    int n = n0 + j * 8 + cq;
                    atomicMax(&g_s.pooled[s0 * LAT + n],     encf(v0 + b3s[n]));
                    atomicMax(&g_s.pooled[s0 * LAT + n + 1], encf(v1 + b3s[n + 1]));
                }
            }
        } else {
            #pragma unroll
            for (int i = 0; i < 4; i++) {
                int r0 = i * 16 + rq;
                int sa = segsCur[r0], sbg = segsCur[r0 + 8];
                #pragma unroll
                for (int j = 0; j < 8; j++) {
                    int n = n0 + j * 8 + cq;
                    atomicMax(&g_s.pooled[sa  * LAT + n],     encf(acc3[i][j][0] + b3s[n]));
                    atomicMax(&g_s.pooled[sa  * LAT + n + 1], encf(acc3[i][j][1] + b3s[n + 1]));
                    atomicMax(&g_s.pooled[sbg * LAT + n],     encf(acc3[i][j][2] + b3s[n]));
                    atomicMax(&g_s.pooled[sbg * LAT + n + 1], encf(acc3[i][j][3] + b3s[n + 1]));
                }
            }
        }

        // carry next tile's fragments
        #pragma unroll
        for (int kt = 0; kt < 4; kt++)
            #pragma unroll
            for (int q = 0; q < 4; q++) A2[kt][q] = A2n[kt][q];
    }
}

__global__ void k_final(const float* __restrict__ Wf,
                        const float* __restrict__ bf,
                        float* __restrict__ out) {
    int g = blockIdx.x, l = threadIdx.x;
    float a0 = 0.f, a1 = 0.f, a2 = 0.f;
    int j0 = 4 * l;
    #pragma unroll
    for (int h = 0; h < 2; h++) {
        uint4 p = *(const uint4*)&g_s.pooled[g * LAT + h * 128 + j0];
        float v[4] = { decf(p.x), decf(p.y), decf(p.z), decf(p.w) };
        #pragma unroll
        for (int i = 0; i < 4; i++) {
            int j = h * 128 + j0 + i;
            a0 = fmaf(v[i], Wf[j * 3 + 0], a0);
            a1 = fmaf(v[i], Wf[j * 3 + 1], a1);
            a2 = fmaf(v[i], Wf[j * 3 + 2], a2);
        }
    }
    #pragma unroll
    for (int o = 16; o > 0; o >>= 1) {
        a0 += __shfl_down_sync(0xffffffffu, a0, o);
        a1 += __shfl_down_sync(0xffffffffu, a1, o);
        a2 += __shfl_down_sync(0xffffffffu, a2, o);
    }
    if (l == 0) {
        float inv = 1.f / fmaxf(g_s.cnt[g], 1.f);
        out[g * 3 + 0] = g_s.csum[g * 3 + 0] * inv + softplus_f(a0 + bf[0]);
        out[g * 3 + 1] = g_s.csum[g * 3 + 1] * inv + softplus_f(a1 + bf[1]);
        out[g * 3 + 2] = g_s.csum[g * 3 + 2] * inv + softplus_f(a2 + bf[2]);
    }
}

// ---------------- launch --------------------------------------------------
extern "C" void kernel_launch(void* const* d_in, const int* in_sizes, int n_in,
                              void* d_out, int out_size) {
    const float* pc = (const float*)d_in[0];
    const float* W1 = (const float*)d_in[1];
    const float* b1 = (const float*)d_in[2];
    const float* W2 = (const float*)d_in[3];
    const float* b2 = (const float*)d_in[4];
    const float* W3 = (const float*)d_in[5];
    const float* b3 = (const float*)d_in[6];
    const float* Wf = (const float*)d_in[7];
    const float* bf = (const float*)d_in[8];
    const int*   sg = (const int*)d_in[9];
    float* out = (float*)d_out;
    (void)in_sizes; (void)n_in; (void)out_size;

    cudaFuncSetAttribute(k_mlp, cudaFuncAttributeMaxDynamicSharedMemorySize,
                         SMEM_TOTAL);
    int sms = 148;
    cudaDeviceGetAttribute(&sms, cudaDevAttrMultiProcessorCount, 0);

    // launch pattern [k_zero, k_mlp, k_final, k_tail]: ncu -s 5 -c 1
    // lands on launch #6 == the 2nd call's k_mlp.
    k_zero<<<64, 256>>>();
    k_mlp<<<sms * 2, THREADS, SMEM_TOTAL>>>(pc, W1, b1, W2, b2, W3, b3, sg);
    k_final<<<G, 32>>>(Wf, bf, out);
    k_tail<<<1, 32>>>();
}

// round 11
// speedup vs baseline: 1.0774x; 1.0774x over previous
#include <cuda_runtime.h>
#include <cuda_fp16.h>
#include <cstdint>
#include <math.h>

#define N_PTS 1000000
#define G     256
#define H1C   64
#define H2C   128
#define LAT   256
#define TILE  64
#define NT    15625         // 1e6 / 64 exactly
#define THREADS 128

// ---------------- scratch (single struct -> one memset) ------------------
struct Scratch {
    unsigned pooled[G * LAT];
    float    csum[G * 3];
    float    cnt[G];
};
__device__ Scratch g_s;

__device__ __forceinline__ unsigned encf(float f) {
    unsigned u = __float_as_uint(f);
    return (u & 0x80000000u) ? ~u : (u | 0x80000000u);
}
__device__ __forceinline__ float decf(unsigned u) {
    return (u & 0x80000000u) ? __uint_as_float(u ^ 0x80000000u)
                             : __uint_as_float(~u);
}
__device__ __forceinline__ float softplus_f(float x) {
    return fmaxf(x, 0.f) + log1pf(expf(-fabsf(x)));
}

// ---------------- mma.sync helpers --------------------------------------
__device__ __forceinline__ uint32_t smem_u32(const void* p) {
    uint32_t a;
    asm("{ .reg .u64 t; cvta.to.shared.u64 t, %1; cvt.u32.u64 %0, t; }"
        : "=r"(a) : "l"(p));
    return a;
}
__device__ __forceinline__ void ldsm4(uint32_t r[4], uint32_t a) {
    asm volatile("ldmatrix.sync.aligned.m8n8.x4.shared.b16 {%0,%1,%2,%3}, [%4];"
        : "=r"(r[0]), "=r"(r[1]), "=r"(r[2]), "=r"(r[3]) : "r"(a));
}
__device__ __forceinline__ void mma16816(float d[4], const uint32_t a[4],
                                         uint32_t b0, uint32_t b1) {
    asm volatile(
        "mma.sync.aligned.m16n8k16.row.col.f32.f16.f16.f32 "
        "{%0,%1,%2,%3}, {%4,%5,%6,%7}, {%8,%9}, {%0,%1,%2,%3};"
        : "+f"(d[0]), "+f"(d[1]), "+f"(d[2]), "+f"(d[3])
        : "r"(a[0]), "r"(a[1]), "r"(a[2]), "r"(a[3]), "r"(b0), "r"(b1));
}
__device__ __forceinline__ unsigned pack_f16(float lo, float hi) {
    unsigned r;
    asm("cvt.rn.f16x2.f32 %0, %1, %2;" : "=r"(r) : "f"(hi), "f"(lo));
    return r;  // low 16 bits = lo
}

// ---------------- SMEM layout (bytes; tiles 1024-aligned) ----------------
#define OFF_W3    0         // 2 kblk x 256 x 128B = 65536
#define OFF_W2    65536     // 128 x 128B = 16384
#define OFF_H2    81920     // 2 kblk x 64 x 128B = 16384
#define OFF_FEATS 98304     // 64*4 f = 1024
#define OFF_W1    99328     // 256 f = 1024
#define OFF_B1    100352    // 256
#define OFF_B2    100608    // 512
#define OFF_B3    101120    // 1024
#define OFF_SEGS  102144    // 2 x 64 ints (double buffered) = 512
#define SMEM_TOTAL 102656   // x2 CTAs = 205312 <= 228KB/SM

__global__ __launch_bounds__(THREADS, 2)
void k_mlp(const float* __restrict__ pc,
           const float* __restrict__ W1, const float* __restrict__ b1,
           const float* __restrict__ W2, const float* __restrict__ b2,
           const float* __restrict__ W3, const float* __restrict__ b3,
           const int*   __restrict__ seg) {
    extern __shared__ __align__(1024) char smem[];
    const uint32_t sb = smem_u32(smem);
    const int tid  = threadIdx.x;
    const int w    = tid >> 5;      // 4 warps
    const int lane = tid & 31;
    const bool is64 = (seg[N_PTS - 1] == 0);

    float* feats = (float*)(smem + OFF_FEATS);
    float* W1s   = (float*)(smem + OFF_W1);
    float* b1s   = (float*)(smem + OFF_B1);
    float* b2s   = (float*)(smem + OFF_B2);
    float* b3s   = (float*)(smem + OFF_B3);
    int*   segsA = (int*)  (smem + OFF_SEGS);
    int*   segsB = segsA + TILE;

    // ---- one-time weight prep: transpose to [n][k] fp16, SW128 ----------
    for (int i = tid; i < H1C * H2C; i += THREADS) {      // W2 [k=64][n=128]
        int k = i >> 7, n = i & 127;
        unsigned off = (unsigned)(n * 128) + (((unsigned)(k * 2)) ^ ((n & 7) << 4));
        *(__half*)(smem + OFF_W2 + off) = __float2half_rn(W2[i]);
    }
    for (int i = tid; i < H2C * LAT; i += THREADS) {      // W3 [k=128][n=256]
        int k = i >> 8, n = i & 255;
        unsigned off = (unsigned)((k >> 6) * 32768) + (unsigned)(n * 128)
                     + ((((unsigned)(k & 63)) * 2) ^ ((n & 7) << 4));
        *(__half*)(smem + OFF_W3 + off) = __float2half_rn(W3[i]);
    }
    for (int i = tid; i < 4 * H1C; i += THREADS) W1s[i] = W1[i];
    for (int i = tid; i < H1C;     i += THREADS) b1s[i] = b1[i];
    for (int i = tid; i < H2C;     i += THREADS) b2s[i] = b2[i];
    for (int i = tid; i < LAT;     i += THREADS) b3s[i] = b3[i];

    // per-lane ldmatrix geometry (validated layout)
    const int lane7 = lane & 7;
    const int gA_r = ((lane >> 3) & 1) * 8 + lane7;   // A row offset in 16x16
    const int gA_c = ((lane >> 4) & 1) * 8;           // A col offset
    const int gB_r = ((lane >> 4) & 1) * 8 + lane7;   // B n offset
    const int gB_c = ((lane >> 3) & 1) * 8;           // B k offset
    const unsigned xmA = (unsigned)lane7 << 4;        // swizzle (row&7)<<4
    const int rq = lane >> 2;                         // c-frag row-in-8
    const int cq = 2 * (lane & 3);                    // c-frag col pair

    // ---- prefetch first tile into registers (tid<64: one point each) ----
    float pf1 = 0.f, pf2 = 0.f, pf3 = 0.f, pf4 = 0.f;
    int   pfs = 0;
    if (tid < TILE) {
        long gp = (long)blockIdx.x * TILE + tid;
        pf1 = pc[gp * 5 + 1]; pf2 = pc[gp * 5 + 2];
        pf3 = pc[gp * 5 + 3]; pf4 = pc[gp * 5 + 4];
        pfs = is64 ? seg[2 * gp] : seg[gp];
    }

    int it = 0;
    for (long t = blockIdx.x; t < NT; t += gridDim.x, it++) {
        int* segs = (it & 1) ? segsB : segsA;

        // ---- commit prefetched tile + fused centroid --------------------
        if (tid < TILE) {
            feats[tid * 4 + 0] = pf4;
            feats[tid * 4 + 1] = pf1;
            feats[tid * 4 + 2] = pf2;
            feats[tid * 4 + 3] = pf3;
            segs[tid] = pfs;
            float x = pf1, y = pf2, z = pf3, cn = 1.f;
            int s = pfs;
            int s0 = __shfl_sync(0xffffffffu, s, 0);
            if (__all_sync(0xffffffffu, s == s0)) {
                #pragma unroll
                for (int o = 16; o > 0; o >>= 1) {
                    x  += __shfl_down_sync(0xffffffffu, x,  o);
                    y  += __shfl_down_sync(0xffffffffu, y,  o);
                    z  += __shfl_down_sync(0xffffffffu, z,  o);
                    cn += __shfl_down_sync(0xffffffffu, cn, o);
                }
                if (lane == 0) {
                    atomicAdd(&g_s.csum[s * 3 + 0], x);
                    atomicAdd(&g_s.csum[s * 3 + 1], y);
                    atomicAdd(&g_s.csum[s * 3 + 2], z);
                    atomicAdd(&g_s.cnt[s], cn);
                }
            } else {
                atomicAdd(&g_s.csum[s * 3 + 0], x);
                atomicAdd(&g_s.csum[s * 3 + 1], y);
                atomicAdd(&g_s.csum[s * 3 + 2], z);
                atomicAdd(&g_s.cnt[s], 1.f);
            }
            // ---- issue next-tile prefetch NOW (overlaps layers 1-3) -----
            long tn = t + gridDim.x;
            if (tn < NT) {
                long gp = tn * TILE + tid;
                pf1 = pc[gp * 5 + 1]; pf2 = pc[gp * 5 + 2];
                pf3 = pc[gp * 5 + 3]; pf4 = pc[gp * 5 + 4];
                pfs = is64 ? seg[2 * gp] : seg[gp];
            }
        }
        __syncthreads();                     // sync1: feats/segs ready

        // ==== fused layers 1+2: warp owns rows [16w, 16w+16) =============
        {
            const int ra = w * 16 + rq;      // this lane's rows: ra, ra+8
            float fa0 = feats[ra * 4 + 0], fa1 = feats[ra * 4 + 1];
            float fa2 = feats[ra * 4 + 2], fa3 = feats[ra * 4 + 3];
            float fb0 = feats[(ra + 8) * 4 + 0], fb1 = feats[(ra + 8) * 4 + 1];
            float fb2 = feats[(ra + 8) * 4 + 2], fb3 = feats[(ra + 8) * 4 + 3];
            uint32_t A2[4][4];
            #pragma unroll
            for (int kt = 0; kt < 4; kt++) {
                const int c0 = kt * 16 + cq;           // cols c0,c0+1,c0+8,c0+9
                float2 sa0 = *(const float2*)&b1s[c0];
                float2 sa1 = *(const float2*)&b1s[c0 + 8];
                float2 ta0 = sa0, ta1 = sa1;
                #pragma unroll
                for (int j = 0; j < 4; j++) {
                    float2 w0 = *(const float2*)&W1s[j * 64 + c0];
                    float2 w1 = *(const float2*)&W1s[j * 64 + c0 + 8];
                    float fj_a = (j == 0) ? fa0 : (j == 1) ? fa1 : (j == 2) ? fa2 : fa3;
                    float fj_b = (j == 0) ? fb0 : (j == 1) ? fb1 : (j == 2) ? fb2 : fb3;
                    sa0.x = fmaf(fj_a, w0.x, sa0.x); sa0.y = fmaf(fj_a, w0.y, sa0.y);
                    sa1.x = fmaf(fj_a, w1.x, sa1.x); sa1.y = fmaf(fj_a, w1.y, sa1.y);
                    ta0.x = fmaf(fj_b, w0.x, ta0.x); ta0.y = fmaf(fj_b, w0.y, ta0.y);
                    ta1.x = fmaf(fj_b, w1.x, ta1.x); ta1.y = fmaf(fj_b, w1.y, ta1.y);
                }
                A2[kt][0] = pack_f16(fmaxf(sa0.x, 0.f), fmaxf(sa0.y, 0.f));
                A2[kt][1] = pack_f16(fmaxf(ta0.x, 0.f), fmaxf(ta0.y, 0.f));
                A2[kt][2] = pack_f16(fmaxf(sa1.x, 0.f), fmaxf(sa1.y, 0.f));
                A2[kt][3] = pack_f16(fmaxf(ta1.x, 0.f), fmaxf(ta1.y, 0.f));
            }

            // layer 2: C2(16 x 128) = A2 @ W2
            float acc2[16][4];
            #pragma unroll
            for (int nb = 0; nb < 16; nb++)
                #pragma unroll
                for (int q = 0; q < 4; q++) acc2[nb][q] = 0.f;
            #pragma unroll
            for (int kt = 0; kt < 4; kt++) {
                const int k0 = kt * 16;
                #pragma unroll
                for (int nbp = 0; nbp < 8; nbp++) {
                    uint32_t Bt[4];
                    unsigned boff = (unsigned)((nbp * 16 + gB_r) * 128)
                                  + (((unsigned)((k0 + gB_c) * 2)) ^ xmA);
                    ldsm4(Bt, sb + OFF_W2 + boff);
                    mma16816(acc2[2 * nbp + 0], A2[kt], Bt[0], Bt[1]);
                    mma16816(acc2[2 * nbp + 1], A2[kt], Bt[2], Bt[3]);
                }
            }

            // epilogue: bias+relu -> h2 fp16 (n becomes k), swizzled STS
            #pragma unroll
            for (int nb = 0; nb < 16; nb++) {
                const int n = nb * 8 + cq;
                float2 bb = *(const float2*)&b2s[n];
                float v0 = fmaxf(acc2[nb][0] + bb.x, 0.f);
                float v1 = fmaxf(acc2[nb][1] + bb.y, 0.f);
                float v2 = fmaxf(acc2[nb][2] + bb.x, 0.f);
                float v3 = fmaxf(acc2[nb][3] + bb.y, 0.f);
                unsigned blk = (unsigned)((n >> 6) * 8192);
                unsigned cb  = ((unsigned)((n & 63) * 2)) ^ ((unsigned)rq << 4);
                *(unsigned*)(smem + OFF_H2 + blk + (unsigned)(ra * 128) + cb)
                    = pack_f16(v0, v1);
                *(unsigned*)(smem + OFF_H2 + blk + (unsigned)((ra + 8) * 128) + cb)
                    = pack_f16(v2, v3);
            }
        }
        __syncthreads();                     // sync2: h2 ready

        // ---- layer 3: C3(64x256) = h2 @ W3; warp = (64 rows, 64 n)
        float acc3[4][8][4];
        #pragma unroll
        for (int i = 0; i < 4; i++)
            #pragma unroll
            for (int j = 0; j < 8; j++)
                #pragma unroll
                for (int q = 0; q < 4; q++) acc3[i][j][q] = 0.f;
        const int n0 = w * 64;
        #pragma unroll
        for (int kt = 0; kt < 8; kt++) {
            const int k0 = kt * 16;
            const unsigned kbA = (unsigned)((k0 >> 6) * 8192);
            const unsigned kbB = (unsigned)((k0 >> 6) * 32768);
            const unsigned kby = ((unsigned)(((k0 & 63) + gB_c) * 2)) ^ xmA;
            const unsigned kay = ((unsigned)(((k0 & 63) + gA_c) * 2)) ^ xmA;
            uint32_t Bh[4][4];
            #pragma unroll
            for (int nb = 0; nb < 4; nb++) {
                unsigned boff = kbB + (unsigned)((n0 + nb * 16 + gB_r) * 128) + kby;
                ldsm4(Bh[nb], sb + OFF_W3 + boff);
            }
            #pragma unroll
            for (int i = 0; i < 4; i++) {
                uint32_t Ah[4];
                ldsm4(Ah, sb + OFF_H2 + kbA
                      + (unsigned)((i * 16 + gA_r) * 128) + kay);
                #pragma unroll
                for (int nb = 0; nb < 4; nb++) {
                    mma16816(acc3[i][2 * nb + 0], Ah, Bh[nb][0], Bh[nb][1]);
                    mma16816(acc3[i][2 * nb + 1], Ah, Bh[nb][2], Bh[nb][3]);
                }
            }
        }

        // ---- segment-max pooling epilogue
        if (segs[0] == segs[TILE - 1]) {
            const int s0 = segs[0];
            #pragma unroll
            for (int j = 0; j < 8; j++) {
                float v0 = -3.402823466e38f, v1 = -3.402823466e38f;
                #pragma unroll
                for (int i = 0; i < 4; i++) {
                    v0 = fmaxf(v0, fmaxf(acc3[i][j][0], acc3[i][j][2]));
                    v1 = fmaxf(v1, fmaxf(acc3[i][j][1], acc3[i][j][3]));
                }
                #pragma unroll
                for (int o = 4; o < 32; o <<= 1) {
                    v0 = fmaxf(v0, __shfl_xor_sync(0xffffffffu, v0, o));
                    v1 = fmaxf(v1, __shfl_xor_sync(0xffffffffu, v1, o));
                }
                if (lane < 4) {
                    int n = n0 + j * 8 + cq;
                    atomicMax(&g_s.pooled[s0 * LAT + n],     encf(v0 + b3s[n]));
                    atomicMax(&g_s.pooled[s0 * LAT + n + 1], encf(v1 + b3s[n + 1]));
                }
            }
        } else {
            #pragma unroll
            for (int i = 0; i < 4; i++) {
                int r0 = i * 16 + rq;
                int sa = segs[r0], sbg = segs[r0 + 8];
                #pragma unroll
                for (int j = 0; j < 8; j++) {
                    int n = n0 + j * 8 + cq;
                    atomicMax(&g_s.pooled[sa  * LAT + n],     encf(acc3[i][j][0] + b3s[n]));
                    atomicMax(&g_s.pooled[sa  * LAT + n + 1], encf(acc3[i][j][1] + b3s[n + 1]));
                    atomicMax(&g_s.pooled[sbg * LAT + n],     encf(acc3[i][j][2] + b3s[n]));
                    atomicMax(&g_s.pooled[sbg * LAT + n + 1], encf(acc3[i][j][3] + b3s[n + 1]));
                }
            }
        }
    }
}

__global__ void k_final(const float* __restrict__ Wf,
                        const float* __restrict__ bf,
                        float* __restrict__ out) {
    int g = blockIdx.x, l = threadIdx.x;
    float a0 = 0.f, a1 = 0.f, a2 = 0.f;
    int j0 = 4 * l;
    #pragma unroll
    for (int h = 0; h < 2; h++) {
        uint4 p = *(const uint4*)&g_s.pooled[g * LAT + h * 128 + j0];
        float v[4] = { decf(p.x), decf(p.y), decf(p.z), decf(p.w) };
        #pragma unroll
        for (int i = 0; i < 4; i++) {
            int j = h * 128 + j0 + i;
            a0 = fmaf(v[i], Wf[j * 3 + 0], a0);
            a1 = fmaf(v[i], Wf[j * 3 + 1], a1);
            a2 = fmaf(v[i], Wf[j * 3 + 2], a2);
        }
    }
    #pragma unroll
    for (int o = 16; o > 0; o >>= 1) {
        a0 += __shfl_down_sync(0xffffffffu, a0, o);
        a1 += __shfl_down_sync(0xffffffffu, a1, o);
        a2 += __shfl_down_sync(0xffffffffu, a2, o);
    }
    if (l == 0) {
        float inv = 1.f / fmaxf(g_s.cnt[g], 1.f);
        out[g * 3 + 0] = g_s.csum[g * 3 + 0] * inv + softplus_f(a0 + bf[0]);
        out[g * 3 + 1] = g_s.csum[g * 3 + 1] * inv + softplus_f(a1 + bf[1]);
        out[g * 3 + 2] = g_s.csum[g * 3 + 2] * inv + softplus_f(a2 + bf[2]);
    }
}

// ---------------- launch --------------------------------------------------
extern "C" void kernel_launch(void* const* d_in, const int* in_sizes, int n_in,
                              void* d_out, int out_size) {
    const float* pc = (const float*)d_in[0];
    const float* W1 = (const float*)d_in[1];
    const float* b1 = (const float*)d_in[2];
    const float* W2 = (const float*)d_in[3];
    const float* b2 = (const float*)d_in[4];
    const float* W3 = (const float*)d_in[5];
    const float* b3 = (const float*)d_in[6];
    const float* Wf = (const float*)d_in[7];
    const float* bf = (const float*)d_in[8];
    const int*   sg = (const int*)d_in[9];
    float* out = (float*)d_out;
    (void)in_sizes; (void)n_in; (void)out_size;

    cudaFuncSetAttribute(k_mlp, cudaFuncAttributeMaxDynamicSharedMemorySize,
                         SMEM_TOTAL);
    int sms = 148;
    cudaDeviceGetAttribute(&sms, cudaDevAttrMultiProcessorCount, 0);

    void* scratch_ptr = nullptr;
    cudaGetSymbolAddress(&scratch_ptr, g_s);
    cudaMemsetAsync(scratch_ptr, 0, sizeof(Scratch), 0);

    k_mlp<<<sms * 2, THREADS, SMEM_TOTAL>>>(pc, W1, b1, W2, b2, W3, b3, sg);
    k_final<<<G, 32>>>(Wf, bf, out);
}